// round 14
// baseline (speedup 1.0000x reference)
#include <cuda_runtime.h>

// ---------------- problem constants ----------------
constexpr int B   = 2;
constexpr int CI  = 256;
constexpr int CR  = 128;
constexpr int H   = 384;
constexpr int W   = 384;
constexpr int h_  = 96;
constexpr int w_  = 96;
constexpr int N   = h_ * w_;       // 9216
constexpr int D   = 64;
constexpr int GRP = 8;

// attention tile geometry: 8x4 pixels, 8 threads/pixel (channel octets)
constexpr int TX = 8;
constexpr int TY = 4;
constexpr int HC = TX + 6;         // 14
constexpr int HR = TY + 6;         // 10
constexpr int NCOL = HC * HR;      // 140
constexpr int C4STR = 18;          // float4 stride per col => ≡2 mod 8, conflict-free

// ---------------- scratch ----------------
__device__ float g_locc[B * N];
__device__ float g_gate[B * N];
__device__ float g_q[B * N * D];
__device__ float g_k[B * N * D];
__device__ float g_v[B * N * D];
__device__ float g_msg[B * N * D];
__device__ float g_msgo[B * CI * N];
__device__ float g_qstats[B * GRP * 2];   // [b*16 .. b*16+16)
__device__ float g_kstats[B * GRP * 2];

// ---------------- f32x2 packed-FMA helpers ----------------
__device__ __forceinline__ unsigned long long ffma2(unsigned long long a,
                                                    unsigned long long b,
                                                    unsigned long long c) {
    unsigned long long d;
    asm("fma.rn.f32x2 %0, %1, %2, %3;" : "=l"(d) : "l"(a), "l"(b), "l"(c));
    return d;
}
__device__ __forceinline__ unsigned long long pack2(float x) {
    unsigned long long d;
    asm("mov.b64 %0, {%1, %2};" : "=l"(d)
        : "r"(__float_as_uint(x)), "r"(__float_as_uint(x)));
    return d;
}
__device__ __forceinline__ float2 ffma2v(float2 a, float2 b, float2 c) {
    float2 d;
    asm("fma.rn.f32x2 %0, %1, %2, %3;"
        : "=l"(reinterpret_cast<unsigned long long&>(d))
        : "l"(reinterpret_cast<unsigned long long&>(a)),
          "l"(reinterpret_cast<unsigned long long&>(b)),
          "l"(reinterpret_cast<unsigned long long&>(c)));
    return d;
}

// ================= per-batch front kernel =================
// blocks [0,144): fused avgpool+Wq proj (+GN q stats), 64n x 64o tile
// blocks [144,288): fused maxpool+Wk/Wv proj (+GN k stats)
// blocks [288,324): occ maxpool -> locc/gate
__global__ __launch_bounds__(256) void front_kernel(
    int b,
    const float* __restrict__ img, const float* __restrict__ rad,
    const float* __restrict__ occ,
    const float* __restrict__ Wq, const float* __restrict__ Wk,
    const float* __restrict__ Wv) {
    __shared__ __align__(16) float sm[2 * 2176 + 2048];   // 25.6 KB
    int bid = blockIdx.x;
    int tid = threadIdx.x;

    if (bid < 144) {
        // ---------------- proj_q: 64n x 64o, K-tile 32 ----------------
        float* Ws = sm;            // [c][o] stride 68
        float* Is = sm + 2176;     // [c][n] 32x64
        int n0 = bid * 64;
        int tx = tid & 15;
        int ty = tid >> 4;
        float acc[4][4] = {};

        for (int c0 = 0; c0 < CI; c0 += 32) {
            for (int i = tid; i < 2048; i += 256) {
                int c = i & 31, o = i >> 5;
                Ws[c * 68 + o] = Wq[o * CI + c0 + c];
            }
            for (int i = tid; i < 2048; i += 256) {
                int c = i >> 6, x = i & 63;
                int n = n0 + x;
                int yy = n / 96, xx = n - yy * 96;
                const float* p = img + (((size_t)(b * CI + c0 + c) * H + yy * 4) * W) + xx * 4;
                float s = 0.f;
#pragma unroll
                for (int r = 0; r < 4; r++) {
                    float4 v = __ldcs((const float4*)(p + r * W));
                    s += v.x + v.y + v.z + v.w;
                }
                Is[c * 64 + x] = s * 0.0625f;
            }
            __syncthreads();
#pragma unroll
            for (int c = 0; c < 32; c++) {
                float4 a4 = *(const float4*)&Ws[c * 68 + ty * 4];
                float4 b4 = *(const float4*)&Is[c * 64 + tx * 4];
                acc[0][0] += a4.x * b4.x; acc[0][1] += a4.x * b4.y;
                acc[0][2] += a4.x * b4.z; acc[0][3] += a4.x * b4.w;
                acc[1][0] += a4.y * b4.x; acc[1][1] += a4.y * b4.y;
                acc[1][2] += a4.y * b4.z; acc[1][3] += a4.y * b4.w;
                acc[2][0] += a4.z * b4.x; acc[2][1] += a4.z * b4.y;
                acc[2][2] += a4.z * b4.z; acc[2][3] += a4.z * b4.w;
                acc[3][0] += a4.w * b4.x; acc[3][1] += a4.w * b4.y;
                acc[3][2] += a4.w * b4.z; acc[3][3] += a4.w * b4.w;
            }
            __syncthreads();
        }

        float s = 0.f, s2 = 0.f;
#pragma unroll
        for (int j = 0; j < 4; j++) {
            float4 o4 = make_float4(acc[0][j], acc[1][j], acc[2][j], acc[3][j]);
            *(float4*)(g_q + ((size_t)(b * N + n0 + tx * 4 + j)) * 64 + ty * 4) = o4;
            s  += o4.x + o4.y + o4.z + o4.w;
            s2 += o4.x * o4.x + o4.y * o4.y + o4.z * o4.z + o4.w * o4.w;
        }
#pragma unroll
        for (int off = 16; off; off >>= 1) {
            s  += __shfl_down_sync(0xffffffffu, s,  off);
            s2 += __shfl_down_sync(0xffffffffu, s2, off);
        }
        if ((tid & 31) == 0) {
            int g = tid >> 5;
            atomicAdd(&g_qstats[(b * 8 + g) * 2 + 0], s);
            atomicAdd(&g_qstats[(b * 8 + g) * 2 + 1], s2);
        }
    } else if (bid < 288) {
        // ---------------- proj_kv: 64n x 64o ----------------
        float* Wks = sm;
        float* Wvs = sm + 2176;
        float* Is  = sm + 4352;
        int n0 = (bid - 144) * 64;
        int tx = tid & 15;
        int ty = tid >> 4;
        float ak[4][4] = {};
        float av[4][4] = {};

        for (int c0 = 0; c0 < CR; c0 += 32) {
            for (int i = tid; i < 2048; i += 256) {
                int c = i & 31, o = i >> 5;
                Wks[c * 68 + o] = Wk[o * CR + c0 + c];
                Wvs[c * 68 + o] = Wv[o * CR + c0 + c];
            }
            for (int i = tid; i < 2048; i += 256) {
                int c = i >> 6, x = i & 63;
                int n = n0 + x;
                int yy = n / 96, xx = n - yy * 96;
                const float* p = rad + (((size_t)(b * CR + c0 + c) * H + yy * 4) * W) + xx * 4;
                float m = -3.4e38f;
#pragma unroll
                for (int r = 0; r < 4; r++) {
                    float4 v = __ldcs((const float4*)(p + r * W));
                    m = fmaxf(m, fmaxf(fmaxf(v.x, v.y), fmaxf(v.z, v.w)));
                }
                Is[c * 64 + x] = m;
            }
            __syncthreads();
#pragma unroll
            for (int c = 0; c < 32; c++) {
                float4 ka = *(const float4*)&Wks[c * 68 + ty * 4];
                float4 va = *(const float4*)&Wvs[c * 68 + ty * 4];
                float4 b4 = *(const float4*)&Is[c * 64 + tx * 4];
                ak[0][0] += ka.x * b4.x; ak[0][1] += ka.x * b4.y;
                ak[0][2] += ka.x * b4.z; ak[0][3] += ka.x * b4.w;
                ak[1][0] += ka.y * b4.x; ak[1][1] += ka.y * b4.y;
                ak[1][2] += ka.y * b4.z; ak[1][3] += ka.y * b4.w;
                ak[2][0] += ka.z * b4.x; ak[2][1] += ka.z * b4.y;
                ak[2][2] += ka.z * b4.z; ak[2][3] += ka.z * b4.w;
                ak[3][0] += ka.w * b4.x; ak[3][1] += ka.w * b4.y;
                ak[3][2] += ka.w * b4.z; ak[3][3] += ka.w * b4.w;
                av[0][0] += va.x * b4.x; av[0][1] += va.x * b4.y;
                av[0][2] += va.x * b4.z; av[0][3] += va.x * b4.w;
                av[1][0] += va.y * b4.x; av[1][1] += va.y * b4.y;
                av[1][2] += va.y * b4.z; av[1][3] += va.y * b4.w;
                av[2][0] += va.z * b4.x; av[2][1] += va.z * b4.y;
                av[2][2] += va.z * b4.z; av[2][3] += va.z * b4.w;
                av[3][0] += va.w * b4.x; av[3][1] += va.w * b4.y;
                av[3][2] += va.w * b4.z; av[3][3] += va.w * b4.w;
            }
            __syncthreads();
        }

        float s = 0.f, s2 = 0.f;
#pragma unroll
        for (int j = 0; j < 4; j++) {
            size_t row = ((size_t)(b * N + n0 + tx * 4 + j)) * 64 + ty * 4;
            float4 k4 = make_float4(ak[0][j], ak[1][j], ak[2][j], ak[3][j]);
            float4 v4 = make_float4(av[0][j], av[1][j], av[2][j], av[3][j]);
            *(float4*)(g_k + row) = k4;
            *(float4*)(g_v + row) = v4;
            s  += k4.x + k4.y + k4.z + k4.w;
            s2 += k4.x * k4.x + k4.y * k4.y + k4.z * k4.z + k4.w * k4.w;
        }
#pragma unroll
        for (int off = 16; off; off >>= 1) {
            s  += __shfl_down_sync(0xffffffffu, s,  off);
            s2 += __shfl_down_sync(0xffffffffu, s2, off);
        }
        if ((tid & 31) == 0) {
            int g = tid >> 5;
            atomicAdd(&g_kstats[(b * 8 + g) * 2 + 0], s);
            atomicAdd(&g_kstats[(b * 8 + g) * 2 + 1], s2);
        }
    } else {
        // ---------------- pool_occ (per batch) ----------------
        int t = (bid - 288) * 256 + tid;
        if (t >= N) return;
        int x = t % w_;
        int y = t / w_;
        const float* p = occ + ((size_t)b * H + y * 4) * W + x * 4;
        float m = -3.4e38f;
#pragma unroll
        for (int r = 0; r < 4; r++) {
            float4 v = __ldcs((const float4*)(p + r * W));
            m = fmaxf(m, fmaxf(fmaxf(v.x, v.y), fmaxf(v.z, v.w)));
        }
        g_locc[b * N + t] = 2.f * logf(fmaxf(m, 1e-6f));
        g_gate[b * N + t] = fminf(fmaxf(m, 0.f), 1.f);
    }
}

// ------------- attention: 8 threads/pixel (per batch) ----------------
__global__ __launch_bounds__(256, 4)
void attn_kernel(int b,
                 const float* __restrict__ gq_w, const float* __restrict__ gq_b,
                 const float* __restrict__ gk_w, const float* __restrict__ gk_b) {
    __shared__ float4 kv_s[NCOL * C4STR];
    __shared__ float  w_s[32 * 49];
    __shared__ float  locc_s[NCOL];
    __shared__ float  sQA[64], sQB[64], sAk[64], sBk[64];

    int x0 = blockIdx.x * TX, y0 = blockIdx.y * TY;
    int tid  = threadIdx.x;
    int wrp  = tid >> 5;
    int lane = tid & 31;
    int r    = wrp >> 1;
    int pix  = (wrp & 1) * 4 + (lane & 3);
    int oct  = lane >> 2;

    if (tid < 64) {
        int d = tid, g = d >> 3;
        const float inv = 1.f / (float)(N * 8);
        float su  = g_qstats[(b * 8 + g) * 2 + 0];
        float su2 = g_qstats[(b * 8 + g) * 2 + 1];
        float mu = su * inv;
        float rs = rsqrtf(su2 * inv - mu * mu + 1e-5f);
        float A = rs * gq_w[d];
        sQA[d] = A;
        sQB[d] = gq_b[d] - mu * A;
        su  = g_kstats[(b * 8 + g) * 2 + 0];
        su2 = g_kstats[(b * 8 + g) * 2 + 1];
        mu = su * inv;
        rs = rsqrtf(su2 * inv - mu * mu + 1e-5f);
        A = rs * gk_w[d];
        sAk[d] = A;
        sBk[d] = gk_b[d] - mu * A;
    }

    for (int i = tid; i < NCOL * 16; i += 256) {
        int col = i >> 4, quad = i & 15;
        int rr = col / HC, cc = col - rr * HC;
        int yy = y0 - 3 + rr, xx = x0 - 3 + cc;
        bool ok = ((unsigned)yy < (unsigned)h_) && ((unsigned)xx < (unsigned)w_);
        int nn = b * N + yy * w_ + xx;
        float4 v = make_float4(0.f, 0.f, 0.f, 0.f);
        if (ok) v = *(const float4*)(g_k + (size_t)nn * 64 + quad * 4);
        kv_s[col * C4STR + quad] = v;
        if (quad == 0) locc_s[col] = ok ? g_locc[nn] : 0.f;
    }
    __syncthreads();

    int nq = b * N + (y0 + r) * w_ + x0 + pix;

    float2 qp[4];
    float qB;
    {
        const float* qr = g_q + (size_t)nq * 64;
        float4 qa = *(const float4*)(qr + oct * 4);
        float4 qb = *(const float4*)(qr + 32 + oct * 4);
        int da = oct * 4, db = 32 + oct * 4;
        float n0 = qa.x * sQA[da + 0] + sQB[da + 0];
        float n1 = qa.y * sQA[da + 1] + sQB[da + 1];
        float n2 = qa.z * sQA[da + 2] + sQB[da + 2];
        float n3 = qa.w * sQA[da + 3] + sQB[da + 3];
        float n4 = qb.x * sQA[db + 0] + sQB[db + 0];
        float n5 = qb.y * sQA[db + 1] + sQB[db + 1];
        float n6 = qb.z * sQA[db + 2] + sQB[db + 2];
        float n7 = qb.w * sQA[db + 3] + sQB[db + 3];
        qB = n0 * sBk[da + 0] + n1 * sBk[da + 1] + n2 * sBk[da + 2] + n3 * sBk[da + 3]
           + n4 * sBk[db + 0] + n5 * sBk[db + 1] + n6 * sBk[db + 2] + n7 * sBk[db + 3];
        qp[0] = make_float2(n0 * sAk[da + 0] * 0.125f, n1 * sAk[da + 1] * 0.125f);
        qp[1] = make_float2(n2 * sAk[da + 2] * 0.125f, n3 * sAk[da + 3] * 0.125f);
        qp[2] = make_float2(n4 * sAk[db + 0] * 0.125f, n5 * sAk[db + 1] * 0.125f);
        qp[3] = make_float2(n6 * sAk[db + 2] * 0.125f, n7 * sAk[db + 3] * 0.125f);
    }
    qB += __shfl_xor_sync(0xffffffffu, qB, 4);
    qB += __shfl_xor_sync(0xffffffffu, qB, 8);
    qB += __shfl_xor_sync(0xffffffffu, qB, 16);
    float qB2 = qB * 0.125f;

    const float LPAD = -27.631021115928547f;
    const float4* kbase = &kv_s[(r * HC + pix) * C4STR];

    float lg[7];
    float m_own = -1e30f;

#pragma unroll
    for (int p = 0; p < 49; p++) {
        int dy = p / 7, dx = p - dy * 7;
        const float4* kp = kbase + (dy * HC + dx) * C4STR;
        float4 ka = kp[oct];
        float4 kb = kp[oct + 8];
        float2 a2 = make_float2(0.f, 0.f);
        a2 = ffma2v(qp[0], make_float2(ka.x, ka.y), a2);
        a2 = ffma2v(qp[2], make_float2(kb.x, kb.y), a2);
        float2 b2 = make_float2(0.f, 0.f);
        b2 = ffma2v(qp[1], make_float2(ka.z, ka.w), b2);
        b2 = ffma2v(qp[3], make_float2(kb.z, kb.w), b2);
        float dot = a2.x + a2.y + b2.x + b2.y;
        dot += __shfl_xor_sync(0xffffffffu, dot, 4);
        dot += __shfl_xor_sync(0xffffffffu, dot, 8);
        dot += __shfl_xor_sync(0xffffffffu, dot, 16);

        if (oct == (p & 7)) {
            int yy = y0 + r + dy - 3;
            int xx = x0 + pix + dx - 3;
            bool inb = ((unsigned)yy < (unsigned)h_) && ((unsigned)xx < (unsigned)w_);
            int col = (r + dy) * HC + pix + dx;
            float logit = inb ? (dot + qB2 + locc_s[col]) : LPAD;
            lg[p >> 3] = logit;
            m_own = fmaxf(m_own, logit);
        }
    }

    m_own = fmaxf(m_own, __shfl_xor_sync(0xffffffffu, m_own, 4));
    m_own = fmaxf(m_own, __shfl_xor_sync(0xffffffffu, m_own, 8));
    m_own = fmaxf(m_own, __shfl_xor_sync(0xffffffffu, m_own, 16));
    int px_idx = r * 8 + pix;
    float* wr = &w_s[px_idx * 49];
    float ssum = 0.f;
#pragma unroll
    for (int g = 0; g < 7; g++) {
        if (g < 6 || oct == 0) {
            float e = __expf(lg[g] - m_own);
            ssum += e;
            wr[g * 8 + oct] = e;
        }
    }
    ssum += __shfl_xor_sync(0xffffffffu, ssum, 4);
    ssum += __shfl_xor_sync(0xffffffffu, ssum, 8);
    ssum += __shfl_xor_sync(0xffffffffu, ssum, 16);
    float gs = g_gate[nq] / ssum;

    __syncthreads();
    for (int i = tid; i < NCOL * 16; i += 256) {
        int col = i >> 4, quad = i & 15;
        int rr = col / HC, cc = col - rr * HC;
        int yy = y0 - 3 + rr, xx = x0 - 3 + cc;
        bool ok = ((unsigned)yy < (unsigned)h_) && ((unsigned)xx < (unsigned)w_);
        float4 v = make_float4(0.f, 0.f, 0.f, 0.f);
        if (ok) v = *(const float4*)(g_v + ((size_t)(b * N + yy * w_ + xx)) * 64 + quad * 4);
        kv_s[col * C4STR + quad] = v;
    }
    __syncthreads();

    float2 acc[4];
#pragma unroll
    for (int c = 0; c < 4; c++) acc[c] = make_float2(0.f, 0.f);
#pragma unroll
    for (int p = 0; p < 49; p++) {
        int dy = p / 7, dx = p - dy * 7;
        float wgt = wr[p];
        float2 w2 = make_float2(wgt, wgt);
        const float4* vp = kbase + (dy * HC + dx) * C4STR;
        float4 va = vp[oct];
        float4 vb = vp[oct + 8];
        acc[0] = ffma2v(w2, make_float2(va.x, va.y), acc[0]);
        acc[1] = ffma2v(w2, make_float2(va.z, va.w), acc[1]);
        acc[2] = ffma2v(w2, make_float2(vb.x, vb.y), acc[2]);
        acc[3] = ffma2v(w2, make_float2(vb.z, vb.w), acc[3]);
    }
    float* mp = g_msg + (size_t)nq * 64;
    *(float4*)(mp + oct * 4)      = make_float4(acc[0].x * gs, acc[0].y * gs,
                                                acc[1].x * gs, acc[1].y * gs);
    *(float4*)(mp + 32 + oct * 4) = make_float4(acc[2].x * gs, acc[2].y * gs,
                                                acc[3].x * gs, acc[3].y * gs);
}

// ---------------- Wo projection with packed f32x2 FMA (per batch) ---------
__global__ __launch_bounds__(256) void wo_kernel(int b, const float* __restrict__ Wo) {
    __shared__ float Ws[32 * 132];
    __shared__ float Ms[32 * 132];
    int co0 = blockIdx.y * 128;
    int n0  = blockIdx.x * 128;
    int tid = threadIdx.x;
    int tx = tid & 15;
    int ty = tid >> 4;

    unsigned long long acc[8][4] = {};

    for (int kc = 0; kc < 2; kc++) {
        int d0 = kc * 32;
        for (int idx = tid; idx < 1024; idx += 256) {
            int r = idx >> 3, dq = idx & 7;
            float4 v = *(const float4*)(Wo + (size_t)(co0 + r) * 64 + d0 + dq * 4);
            Ws[(dq * 4 + 0) * 132 + r] = v.x;
            Ws[(dq * 4 + 1) * 132 + r] = v.y;
            Ws[(dq * 4 + 2) * 132 + r] = v.z;
            Ws[(dq * 4 + 3) * 132 + r] = v.w;
            float4 u = *(const float4*)(g_msg + ((size_t)(b * N + n0 + r)) * 64 + d0 + dq * 4);
            Ms[(dq * 4 + 0) * 132 + r] = u.x;
            Ms[(dq * 4 + 1) * 132 + r] = u.y;
            Ms[(dq * 4 + 2) * 132 + r] = u.z;
            Ms[(dq * 4 + 3) * 132 + r] = u.w;
        }
        __syncthreads();
#pragma unroll
        for (int d = 0; d < 32; d++) {
            unsigned long long b2[4];
#pragma unroll
            for (int jp = 0; jp < 4; jp++)
                b2[jp] = *(const unsigned long long*)&Ms[d * 132 + tx * 8 + jp * 2];
#pragma unroll
            for (int i = 0; i < 8; i++) {
                unsigned long long a2 = pack2(Ws[d * 132 + ty * 8 + i]);
#pragma unroll
                for (int jp = 0; jp < 4; jp++)
                    acc[i][jp] = ffma2(a2, b2[jp], acc[i][jp]);
            }
        }
        __syncthreads();
    }
#pragma unroll
    for (int i = 0; i < 8; i++) {
        float2 r0 = *(float2*)&acc[i][0];
        float2 r1 = *(float2*)&acc[i][1];
        float2 r2 = *(float2*)&acc[i][2];
        float2 r3 = *(float2*)&acc[i][3];
        float* dst = g_msgo + ((size_t)(b * CI + co0 + ty * 8 + i)) * N + n0 + tx * 8;
        *(float4*)dst       = make_float4(r0.x, r0.y, r1.x, r1.y);
        *(float4*)(dst + 4) = make_float4(r2.x, r2.y, r3.x, r3.y);
    }
}

// ------- bilinear x4 upsample + residual (per batch); zero own stats ------
__global__ void upsample_add(int b, const float* __restrict__ img,
                             const float* __restrict__ alpha,
                             float* __restrict__ out) {
    if (blockIdx.x == 0 && threadIdx.x < 32) {
        if (threadIdx.x < 16) g_qstats[b * 16 + threadIdx.x] = 0.f;
        else                  g_kstats[b * 16 + threadIdx.x - 16] = 0.f;
    }
    int t = blockIdx.x * blockDim.x + threadIdx.x;
    if (t >= CI * H * 48) return;
    int k2 = t % 48;
    int Y  = (t / 48) % H;
    int ch = t / (48 * H);

    int m = Y >> 2, i = Y & 3;
    int y0, y1;
    float wy;
    if (i < 2) { y0 = max(m - 1, 0); y1 = m; wy = (i == 0) ? 0.625f : 0.875f; }
    else       { y0 = m; y1 = min(m + 1, h_ - 1); wy = (i == 2) ? 0.125f : 0.375f; }

    const float* pl = g_msgo + (size_t)(b * CI + ch) * N;
    int x0 = 2 * k2;
    int xm = max(x0 - 1, 0), x1 = x0 + 1, x2 = min(x0 + 2, w_ - 1);
    const float* r0p = pl + y0 * w_;
    const float* r1p = pl + y1 * w_;
    float wy1 = 1.f - wy;
    float pm = wy1 * r0p[xm] + wy * r1p[xm];
    float p0 = wy1 * r0p[x0] + wy * r1p[x0];
    float p1 = wy1 * r0p[x1] + wy * r1p[x1];
    float p2 = wy1 * r0p[x2] + wy * r1p[x2];

    float A = alpha[0];
    size_t base = ((size_t)b * CI * H * 48 + t) * 8;
    float4 i0 = __ldcs((const float4*)(img + base));
    float4 i1 = __ldcs((const float4*)(img + base + 4));
    float4 o0, o1;
    o0.x = i0.x + A * (0.375f * pm + 0.625f * p0);
    o0.y = i0.y + A * (0.125f * pm + 0.875f * p0);
    o0.z = i0.z + A * (0.875f * p0 + 0.125f * p1);
    o0.w = i0.w + A * (0.625f * p0 + 0.375f * p1);
    o1.x = i1.x + A * (0.375f * p0 + 0.625f * p1);
    o1.y = i1.y + A * (0.125f * p0 + 0.875f * p1);
    o1.z = i1.z + A * (0.875f * p1 + 0.125f * p2);
    o1.w = i1.w + A * (0.625f * p1 + 0.375f * p2);
    __stcs((float4*)(out + base),     o0);
    __stcs((float4*)(out + base + 4), o1);
}

// ---- launch: role streams. D = all DRAM-bound kernels (serialized on one
// stream so they never contend); C = compute (attn+wo), overlapped with D. ----
extern "C" void kernel_launch(void* const* d_in, const int* in_sizes, int n_in,
                              void* d_out, int out_size) {
    const float* img_bev  = (const float*)d_in[0];
    const float* rad_bev  = (const float*)d_in[1];
    const float* occ_prob = (const float*)d_in[2];
    const float* Wq    = (const float*)d_in[3];
    const float* Wk    = (const float*)d_in[4];
    const float* Wv    = (const float*)d_in[5];
    const float* Wo    = (const float*)d_in[6];
    const float* gq_w  = (const float*)d_in[7];
    const float* gq_b  = (const float*)d_in[8];
    const float* gk_w  = (const float*)d_in[9];
    const float* gk_b  = (const float*)d_in[10];
    const float* alpha = (const float*)d_in[11];
    float* out = (float*)d_out;

    // Lazily create streams/events on the FIRST (uncaptured) call.
    static cudaStream_t sD, sC;
    static cudaEvent_t ev_root, eF[2], eC[2], ev_doneD, ev_doneC;
    static bool init = false;
    if (!init) {
        cudaStreamCreateWithFlags(&sD, cudaStreamNonBlocking);
        cudaStreamCreateWithFlags(&sC, cudaStreamNonBlocking);
        cudaEventCreateWithFlags(&ev_root, cudaEventDisableTiming);
        cudaEventCreateWithFlags(&eF[0],   cudaEventDisableTiming);
        cudaEventCreateWithFlags(&eF[1],   cudaEventDisableTiming);
        cudaEventCreateWithFlags(&eC[0],   cudaEventDisableTiming);
        cudaEventCreateWithFlags(&eC[1],   cudaEventDisableTiming);
        cudaEventCreateWithFlags(&ev_doneD, cudaEventDisableTiming);
        cudaEventCreateWithFlags(&ev_doneC, cudaEventDisableTiming);
        init = true;
    }

    dim3 ag(w_ / TX, h_ / TY, 1);
    dim3 wg(N / 128, CI / 128, 1);

    // fork from the captured stream
    cudaEventRecord(ev_root, 0);
    cudaStreamWaitEvent(sD, ev_root, 0);

    // ---- DRAM stream: fronts then upsamples, strictly ordered ----
    front_kernel<<<324, 256, 0, sD>>>(0, img_bev, rad_bev, occ_prob, Wq, Wk, Wv);
    cudaEventRecord(eF[0], sD);
    front_kernel<<<324, 256, 0, sD>>>(1, img_bev, rad_bev, occ_prob, Wq, Wk, Wv);
    cudaEventRecord(eF[1], sD);

    // ---- compute stream: attn+wo per batch, gated on its front ----
    cudaStreamWaitEvent(sC, eF[0], 0);
    attn_kernel<<<ag, 256, 0, sC>>>(0, gq_w, gq_b, gk_w, gk_b);
    wo_kernel<<<wg, 256, 0, sC>>>(0, Wo);
    cudaEventRecord(eC[0], sC);
    cudaStreamWaitEvent(sC, eF[1], 0);
    attn_kernel<<<ag, 256, 0, sC>>>(1, gq_w, gq_b, gk_w, gk_b);
    wo_kernel<<<wg, 256, 0, sC>>>(1, Wo);
    cudaEventRecord(eC[1], sC);

    // ---- back on DRAM stream: upsamples gated on their wo ----
    cudaStreamWaitEvent(sD, eC[0], 0);
    upsample_add<<<CI * H * 48 / 256, 256, 0, sD>>>(0, img_bev, alpha, out);
    cudaStreamWaitEvent(sD, eC[1], 0);
    upsample_add<<<CI * H * 48 / 256, 256, 0, sD>>>(1, img_bev, alpha, out);

    // join back to the captured stream
    cudaEventRecord(ev_doneD, sD);
    cudaEventRecord(ev_doneC, sC);
    cudaStreamWaitEvent(0, ev_doneD, 0);
    cudaStreamWaitEvent(0, ev_doneC, 0);
}

// round 15
// speedup vs baseline: 1.2061x; 1.2061x over previous
#include <cuda_runtime.h>

// ---------------- problem constants ----------------
constexpr int B   = 2;
constexpr int CI  = 256;
constexpr int CR  = 128;
constexpr int H   = 384;
constexpr int W   = 384;
constexpr int h_  = 96;
constexpr int w_  = 96;
constexpr int N   = h_ * w_;       // 9216
constexpr int D   = 64;
constexpr int GRP = 8;

// attention tile geometry: 8x4 pixels, 8 threads/pixel (channel octets)
constexpr int TX = 8;
constexpr int TY = 4;
constexpr int HC = TX + 6;         // 14
constexpr int HR = TY + 6;         // 10
constexpr int NCOL = HC * HR;      // 140
constexpr int C4STR = 18;          // float4 stride per col => ≡2 mod 8, conflict-free

// ---------------- scratch ----------------
__device__ float g_locc[B * N];
__device__ float g_gate[B * N];
__device__ float g_q[B * N * D];
__device__ float g_k[B * N * D];
__device__ float g_v[B * N * D];
__device__ float g_msg[B * N * D];
__device__ float g_msgo[B * CI * N];
__device__ float g_qstats[B * GRP * 2];   // [b*16 .. b*16+16)
__device__ float g_kstats[B * GRP * 2];

// ---------------- f32x2 packed-FMA helpers ----------------
__device__ __forceinline__ unsigned long long ffma2(unsigned long long a,
                                                    unsigned long long b,
                                                    unsigned long long c) {
    unsigned long long d;
    asm("fma.rn.f32x2 %0, %1, %2, %3;" : "=l"(d) : "l"(a), "l"(b), "l"(c));
    return d;
}
__device__ __forceinline__ unsigned long long pack2(float x) {
    unsigned long long d;
    asm("mov.b64 %0, {%1, %2};" : "=l"(d)
        : "r"(__float_as_uint(x)), "r"(__float_as_uint(x)));
    return d;
}
__device__ __forceinline__ float2 ffma2v(float2 a, float2 b, float2 c) {
    float2 d;
    asm("fma.rn.f32x2 %0, %1, %2, %3;"
        : "=l"(reinterpret_cast<unsigned long long&>(d))
        : "l"(reinterpret_cast<unsigned long long&>(a)),
          "l"(reinterpret_cast<unsigned long long&>(b)),
          "l"(reinterpret_cast<unsigned long long&>(c)));
    return d;
}

// ================= per-batch front kernel =================
// blocks [0,144): fused avgpool+Wq proj (+GN q stats), 64n x 64o tile
// blocks [144,288): fused maxpool+Wk/Wv proj (+GN k stats)
// blocks [288,324): occ maxpool -> locc/gate
__global__ __launch_bounds__(256) void front_kernel(
    int b,
    const float* __restrict__ img, const float* __restrict__ rad,
    const float* __restrict__ occ,
    const float* __restrict__ Wq, const float* __restrict__ Wk,
    const float* __restrict__ Wv) {
    __shared__ __align__(16) float sm[2 * 2176 + 2048];   // 25.6 KB
    int bid = blockIdx.x;
    int tid = threadIdx.x;

    if (bid < 144) {
        // ---------------- proj_q: 64n x 64o, K-tile 32 ----------------
        float* Ws = sm;            // [c][o] stride 68
        float* Is = sm + 2176;     // [c][n] 32x64
        int n0 = bid * 64;
        int tx = tid & 15;
        int ty = tid >> 4;
        float acc[4][4] = {};

        for (int c0 = 0; c0 < CI; c0 += 32) {
            for (int i = tid; i < 2048; i += 256) {
                int c = i & 31, o = i >> 5;
                Ws[c * 68 + o] = Wq[o * CI + c0 + c];
            }
            for (int i = tid; i < 2048; i += 256) {
                int c = i >> 6, x = i & 63;
                int n = n0 + x;
                int yy = n / 96, xx = n - yy * 96;
                const float* p = img + (((size_t)(b * CI + c0 + c) * H + yy * 4) * W) + xx * 4;
                float s = 0.f;
#pragma unroll
                for (int r = 0; r < 4; r++) {
                    float4 v = __ldcs((const float4*)(p + r * W));
                    s += v.x + v.y + v.z + v.w;
                }
                Is[c * 64 + x] = s * 0.0625f;
            }
            __syncthreads();
#pragma unroll
            for (int c = 0; c < 32; c++) {
                float4 a4 = *(const float4*)&Ws[c * 68 + ty * 4];
                float4 b4 = *(const float4*)&Is[c * 64 + tx * 4];
                acc[0][0] += a4.x * b4.x; acc[0][1] += a4.x * b4.y;
                acc[0][2] += a4.x * b4.z; acc[0][3] += a4.x * b4.w;
                acc[1][0] += a4.y * b4.x; acc[1][1] += a4.y * b4.y;
                acc[1][2] += a4.y * b4.z; acc[1][3] += a4.y * b4.w;
                acc[2][0] += a4.z * b4.x; acc[2][1] += a4.z * b4.y;
                acc[2][2] += a4.z * b4.z; acc[2][3] += a4.z * b4.w;
                acc[3][0] += a4.w * b4.x; acc[3][1] += a4.w * b4.y;
                acc[3][2] += a4.w * b4.z; acc[3][3] += a4.w * b4.w;
            }
            __syncthreads();
        }

        float s = 0.f, s2 = 0.f;
#pragma unroll
        for (int j = 0; j < 4; j++) {
            float4 o4 = make_float4(acc[0][j], acc[1][j], acc[2][j], acc[3][j]);
            *(float4*)(g_q + ((size_t)(b * N + n0 + tx * 4 + j)) * 64 + ty * 4) = o4;
            s  += o4.x + o4.y + o4.z + o4.w;
            s2 += o4.x * o4.x + o4.y * o4.y + o4.z * o4.z + o4.w * o4.w;
        }
#pragma unroll
        for (int off = 16; off; off >>= 1) {
            s  += __shfl_down_sync(0xffffffffu, s,  off);
            s2 += __shfl_down_sync(0xffffffffu, s2, off);
        }
        if ((tid & 31) == 0) {
            int g = tid >> 5;
            atomicAdd(&g_qstats[(b * 8 + g) * 2 + 0], s);
            atomicAdd(&g_qstats[(b * 8 + g) * 2 + 1], s2);
        }
    } else if (bid < 288) {
        // ---------------- proj_kv: 64n x 64o ----------------
        float* Wks = sm;
        float* Wvs = sm + 2176;
        float* Is  = sm + 4352;
        int n0 = (bid - 144) * 64;
        int tx = tid & 15;
        int ty = tid >> 4;
        float ak[4][4] = {};
        float av[4][4] = {};

        for (int c0 = 0; c0 < CR; c0 += 32) {
            for (int i = tid; i < 2048; i += 256) {
                int c = i & 31, o = i >> 5;
                Wks[c * 68 + o] = Wk[o * CR + c0 + c];
                Wvs[c * 68 + o] = Wv[o * CR + c0 + c];
            }
            for (int i = tid; i < 2048; i += 256) {
                int c = i >> 6, x = i & 63;
                int n = n0 + x;
                int yy = n / 96, xx = n - yy * 96;
                const float* p = rad + (((size_t)(b * CR + c0 + c) * H + yy * 4) * W) + xx * 4;
                float m = -3.4e38f;
#pragma unroll
                for (int r = 0; r < 4; r++) {
                    float4 v = __ldcs((const float4*)(p + r * W));
                    m = fmaxf(m, fmaxf(fmaxf(v.x, v.y), fmaxf(v.z, v.w)));
                }
                Is[c * 64 + x] = m;
            }
            __syncthreads();
#pragma unroll
            for (int c = 0; c < 32; c++) {
                float4 ka = *(const float4*)&Wks[c * 68 + ty * 4];
                float4 va = *(const float4*)&Wvs[c * 68 + ty * 4];
                float4 b4 = *(const float4*)&Is[c * 64 + tx * 4];
                ak[0][0] += ka.x * b4.x; ak[0][1] += ka.x * b4.y;
                ak[0][2] += ka.x * b4.z; ak[0][3] += ka.x * b4.w;
                ak[1][0] += ka.y * b4.x; ak[1][1] += ka.y * b4.y;
                ak[1][2] += ka.y * b4.z; ak[1][3] += ka.y * b4.w;
                ak[2][0] += ka.z * b4.x; ak[2][1] += ka.z * b4.y;
                ak[2][2] += ka.z * b4.z; ak[2][3] += ka.z * b4.w;
                ak[3][0] += ka.w * b4.x; ak[3][1] += ka.w * b4.y;
                ak[3][2] += ka.w * b4.z; ak[3][3] += ka.w * b4.w;
                av[0][0] += va.x * b4.x; av[0][1] += va.x * b4.y;
                av[0][2] += va.x * b4.z; av[0][3] += va.x * b4.w;
                av[1][0] += va.y * b4.x; av[1][1] += va.y * b4.y;
                av[1][2] += va.y * b4.z; av[1][3] += va.y * b4.w;
                av[2][0] += va.z * b4.x; av[2][1] += va.z * b4.y;
                av[2][2] += va.z * b4.z; av[2][3] += va.z * b4.w;
                av[3][0] += va.w * b4.x; av[3][1] += va.w * b4.y;
                av[3][2] += va.w * b4.z; av[3][3] += va.w * b4.w;
            }
            __syncthreads();
        }

        float s = 0.f, s2 = 0.f;
#pragma unroll
        for (int j = 0; j < 4; j++) {
            size_t row = ((size_t)(b * N + n0 + tx * 4 + j)) * 64 + ty * 4;
            float4 k4 = make_float4(ak[0][j], ak[1][j], ak[2][j], ak[3][j]);
            float4 v4 = make_float4(av[0][j], av[1][j], av[2][j], av[3][j]);
            *(float4*)(g_k + row) = k4;
            *(float4*)(g_v + row) = v4;
            s  += k4.x + k4.y + k4.z + k4.w;
            s2 += k4.x * k4.x + k4.y * k4.y + k4.z * k4.z + k4.w * k4.w;
        }
#pragma unroll
        for (int off = 16; off; off >>= 1) {
            s  += __shfl_down_sync(0xffffffffu, s,  off);
            s2 += __shfl_down_sync(0xffffffffu, s2, off);
        }
        if ((tid & 31) == 0) {
            int g = tid >> 5;
            atomicAdd(&g_kstats[(b * 8 + g) * 2 + 0], s);
            atomicAdd(&g_kstats[(b * 8 + g) * 2 + 1], s2);
        }
    } else {
        // ---------------- pool_occ (per batch) ----------------
        int t = (bid - 288) * 256 + tid;
        if (t >= N) return;
        int x = t % w_;
        int y = t / w_;
        const float* p = occ + ((size_t)b * H + y * 4) * W + x * 4;
        float m = -3.4e38f;
#pragma unroll
        for (int r = 0; r < 4; r++) {
            float4 v = __ldcs((const float4*)(p + r * W));
            m = fmaxf(m, fmaxf(fmaxf(v.x, v.y), fmaxf(v.z, v.w)));
        }
        g_locc[b * N + t] = 2.f * logf(fmaxf(m, 1e-6f));
        g_gate[b * N + t] = fminf(fmaxf(m, 0.f), 1.f);
    }
}

// ------------- attention: 8 threads/pixel (per batch) ----------------
__global__ __launch_bounds__(256, 4)
void attn_kernel(int b,
                 const float* __restrict__ gq_w, const float* __restrict__ gq_b,
                 const float* __restrict__ gk_w, const float* __restrict__ gk_b) {
    __shared__ float4 kv_s[NCOL * C4STR];
    __shared__ float  w_s[32 * 49];
    __shared__ float  locc_s[NCOL];
    __shared__ float  sQA[64], sQB[64], sAk[64], sBk[64];

    int x0 = blockIdx.x * TX, y0 = blockIdx.y * TY;
    int tid  = threadIdx.x;
    int wrp  = tid >> 5;
    int lane = tid & 31;
    int r    = wrp >> 1;
    int pix  = (wrp & 1) * 4 + (lane & 3);
    int oct  = lane >> 2;

    if (tid < 64) {
        int d = tid, g = d >> 3;
        const float inv = 1.f / (float)(N * 8);
        float su  = g_qstats[(b * 8 + g) * 2 + 0];
        float su2 = g_qstats[(b * 8 + g) * 2 + 1];
        float mu = su * inv;
        float rs = rsqrtf(su2 * inv - mu * mu + 1e-5f);
        float A = rs * gq_w[d];
        sQA[d] = A;
        sQB[d] = gq_b[d] - mu * A;
        su  = g_kstats[(b * 8 + g) * 2 + 0];
        su2 = g_kstats[(b * 8 + g) * 2 + 1];
        mu = su * inv;
        rs = rsqrtf(su2 * inv - mu * mu + 1e-5f);
        A = rs * gk_w[d];
        sAk[d] = A;
        sBk[d] = gk_b[d] - mu * A;
    }

    for (int i = tid; i < NCOL * 16; i += 256) {
        int col = i >> 4, quad = i & 15;
        int rr = col / HC, cc = col - rr * HC;
        int yy = y0 - 3 + rr, xx = x0 - 3 + cc;
        bool ok = ((unsigned)yy < (unsigned)h_) && ((unsigned)xx < (unsigned)w_);
        int nn = b * N + yy * w_ + xx;
        float4 v = make_float4(0.f, 0.f, 0.f, 0.f);
        if (ok) v = *(const float4*)(g_k + (size_t)nn * 64 + quad * 4);
        kv_s[col * C4STR + quad] = v;
        if (quad == 0) locc_s[col] = ok ? g_locc[nn] : 0.f;
    }
    __syncthreads();

    int nq = b * N + (y0 + r) * w_ + x0 + pix;

    float2 qp[4];
    float qB;
    {
        const float* qr = g_q + (size_t)nq * 64;
        float4 qa = *(const float4*)(qr + oct * 4);
        float4 qb = *(const float4*)(qr + 32 + oct * 4);
        int da = oct * 4, db = 32 + oct * 4;
        float n0 = qa.x * sQA[da + 0] + sQB[da + 0];
        float n1 = qa.y * sQA[da + 1] + sQB[da + 1];
        float n2 = qa.z * sQA[da + 2] + sQB[da + 2];
        float n3 = qa.w * sQA[da + 3] + sQB[da + 3];
        float n4 = qb.x * sQA[db + 0] + sQB[db + 0];
        float n5 = qb.y * sQA[db + 1] + sQB[db + 1];
        float n6 = qb.z * sQA[db + 2] + sQB[db + 2];
        float n7 = qb.w * sQA[db + 3] + sQB[db + 3];
        qB = n0 * sBk[da + 0] + n1 * sBk[da + 1] + n2 * sBk[da + 2] + n3 * sBk[da + 3]
           + n4 * sBk[db + 0] + n5 * sBk[db + 1] + n6 * sBk[db + 2] + n7 * sBk[db + 3];
        qp[0] = make_float2(n0 * sAk[da + 0] * 0.125f, n1 * sAk[da + 1] * 0.125f);
        qp[1] = make_float2(n2 * sAk[da + 2] * 0.125f, n3 * sAk[da + 3] * 0.125f);
        qp[2] = make_float2(n4 * sAk[db + 0] * 0.125f, n5 * sAk[db + 1] * 0.125f);
        qp[3] = make_float2(n6 * sAk[db + 2] * 0.125f, n7 * sAk[db + 3] * 0.125f);
    }
    qB += __shfl_xor_sync(0xffffffffu, qB, 4);
    qB += __shfl_xor_sync(0xffffffffu, qB, 8);
    qB += __shfl_xor_sync(0xffffffffu, qB, 16);
    float qB2 = qB * 0.125f;

    const float LPAD = -27.631021115928547f;
    const float4* kbase = &kv_s[(r * HC + pix) * C4STR];

    float lg[7];
    float m_own = -1e30f;

#pragma unroll
    for (int p = 0; p < 49; p++) {
        int dy = p / 7, dx = p - dy * 7;
        const float4* kp = kbase + (dy * HC + dx) * C4STR;
        float4 ka = kp[oct];
        float4 kb = kp[oct + 8];
        float2 a2 = make_float2(0.f, 0.f);
        a2 = ffma2v(qp[0], make_float2(ka.x, ka.y), a2);
        a2 = ffma2v(qp[2], make_float2(kb.x, kb.y), a2);
        float2 b2 = make_float2(0.f, 0.f);
        b2 = ffma2v(qp[1], make_float2(ka.z, ka.w), b2);
        b2 = ffma2v(qp[3], make_float2(kb.z, kb.w), b2);
        float dot = a2.x + a2.y + b2.x + b2.y;
        dot += __shfl_xor_sync(0xffffffffu, dot, 4);
        dot += __shfl_xor_sync(0xffffffffu, dot, 8);
        dot += __shfl_xor_sync(0xffffffffu, dot, 16);

        if (oct == (p & 7)) {
            int yy = y0 + r + dy - 3;
            int xx = x0 + pix + dx - 3;
            bool inb = ((unsigned)yy < (unsigned)h_) && ((unsigned)xx < (unsigned)w_);
            int col = (r + dy) * HC + pix + dx;
            float logit = inb ? (dot + qB2 + locc_s[col]) : LPAD;
            lg[p >> 3] = logit;
            m_own = fmaxf(m_own, logit);
        }
    }

    m_own = fmaxf(m_own, __shfl_xor_sync(0xffffffffu, m_own, 4));
    m_own = fmaxf(m_own, __shfl_xor_sync(0xffffffffu, m_own, 8));
    m_own = fmaxf(m_own, __shfl_xor_sync(0xffffffffu, m_own, 16));
    int px_idx = r * 8 + pix;
    float* wr = &w_s[px_idx * 49];
    float ssum = 0.f;
#pragma unroll
    for (int g = 0; g < 7; g++) {
        if (g < 6 || oct == 0) {
            float e = __expf(lg[g] - m_own);
            ssum += e;
            wr[g * 8 + oct] = e;
        }
    }
    ssum += __shfl_xor_sync(0xffffffffu, ssum, 4);
    ssum += __shfl_xor_sync(0xffffffffu, ssum, 8);
    ssum += __shfl_xor_sync(0xffffffffu, ssum, 16);
    float gs = g_gate[nq] / ssum;

    __syncthreads();
    for (int i = tid; i < NCOL * 16; i += 256) {
        int col = i >> 4, quad = i & 15;
        int rr = col / HC, cc = col - rr * HC;
        int yy = y0 - 3 + rr, xx = x0 - 3 + cc;
        bool ok = ((unsigned)yy < (unsigned)h_) && ((unsigned)xx < (unsigned)w_);
        float4 v = make_float4(0.f, 0.f, 0.f, 0.f);
        if (ok) v = *(const float4*)(g_v + ((size_t)(b * N + yy * w_ + xx)) * 64 + quad * 4);
        kv_s[col * C4STR + quad] = v;
    }
    __syncthreads();

    float2 acc[4];
#pragma unroll
    for (int c = 0; c < 4; c++) acc[c] = make_float2(0.f, 0.f);
#pragma unroll
    for (int p = 0; p < 49; p++) {
        int dy = p / 7, dx = p - dy * 7;
        float wgt = wr[p];
        float2 w2 = make_float2(wgt, wgt);
        const float4* vp = kbase + (dy * HC + dx) * C4STR;
        float4 va = vp[oct];
        float4 vb = vp[oct + 8];
        acc[0] = ffma2v(w2, make_float2(va.x, va.y), acc[0]);
        acc[1] = ffma2v(w2, make_float2(va.z, va.w), acc[1]);
        acc[2] = ffma2v(w2, make_float2(vb.x, vb.y), acc[2]);
        acc[3] = ffma2v(w2, make_float2(vb.z, vb.w), acc[3]);
    }
    float* mp = g_msg + (size_t)nq * 64;
    *(float4*)(mp + oct * 4)      = make_float4(acc[0].x * gs, acc[0].y * gs,
                                                acc[1].x * gs, acc[1].y * gs);
    *(float4*)(mp + 32 + oct * 4) = make_float4(acc[2].x * gs, acc[2].y * gs,
                                                acc[3].x * gs, acc[3].y * gs);
}

// ------- Wo projection, 64co x 128n tiles (higher occupancy) --------------
__global__ __launch_bounds__(256) void wo_kernel(int b, const float* __restrict__ Wo) {
    __shared__ float Ws[32 * 68];    // [d][co]  (64 co + pad)
    __shared__ float Ms[32 * 132];   // [d][n]   (128 n + pad)
    int co0 = blockIdx.y * 64;
    int n0  = blockIdx.x * 128;
    int tid = threadIdx.x;
    int tx = tid & 15;   // n octet (128 n)
    int ty = tid >> 4;   // co quad (64 co)

    unsigned long long acc[4][4] = {};

    for (int kc = 0; kc < 2; kc++) {
        int d0 = kc * 32;
        for (int idx = tid; idx < 512; idx += 256) {
            int r = idx >> 3, dq = idx & 7;
            float4 v = *(const float4*)(Wo + (size_t)(co0 + r) * 64 + d0 + dq * 4);
            Ws[(dq * 4 + 0) * 68 + r] = v.x;
            Ws[(dq * 4 + 1) * 68 + r] = v.y;
            Ws[(dq * 4 + 2) * 68 + r] = v.z;
            Ws[(dq * 4 + 3) * 68 + r] = v.w;
        }
        for (int idx = tid; idx < 1024; idx += 256) {
            int r = idx >> 3, dq = idx & 7;
            float4 u = *(const float4*)(g_msg + ((size_t)(b * N + n0 + r)) * 64 + d0 + dq * 4);
            Ms[(dq * 4 + 0) * 132 + r] = u.x;
            Ms[(dq * 4 + 1) * 132 + r] = u.y;
            Ms[(dq * 4 + 2) * 132 + r] = u.z;
            Ms[(dq * 4 + 3) * 132 + r] = u.w;
        }
        __syncthreads();
#pragma unroll
        for (int d = 0; d < 32; d++) {
            unsigned long long b2[4];
#pragma unroll
            for (int jp = 0; jp < 4; jp++)
                b2[jp] = *(const unsigned long long*)&Ms[d * 132 + tx * 8 + jp * 2];
#pragma unroll
            for (int i = 0; i < 4; i++) {
                unsigned long long a2 = pack2(Ws[d * 68 + ty * 4 + i]);
#pragma unroll
                for (int jp = 0; jp < 4; jp++)
                    acc[i][jp] = ffma2(a2, b2[jp], acc[i][jp]);
            }
        }
        __syncthreads();
    }
#pragma unroll
    for (int i = 0; i < 4; i++) {
        float2 r0 = *(float2*)&acc[i][0];
        float2 r1 = *(float2*)&acc[i][1];
        float2 r2 = *(float2*)&acc[i][2];
        float2 r3 = *(float2*)&acc[i][3];
        float* dst = g_msgo + ((size_t)(b * CI + co0 + ty * 4 + i)) * N + n0 + tx * 8;
        *(float4*)dst       = make_float4(r0.x, r0.y, r1.x, r1.y);
        *(float4*)(dst + 4) = make_float4(r2.x, r2.y, r3.x, r3.y);
    }
}

// ------- bilinear x4 upsample + residual (per batch); zero own stats ------
__global__ void upsample_add(int b, const float* __restrict__ img,
                             const float* __restrict__ alpha,
                             float* __restrict__ out) {
    if (blockIdx.x == 0 && threadIdx.x < 32) {
        if (threadIdx.x < 16) g_qstats[b * 16 + threadIdx.x] = 0.f;
        else                  g_kstats[b * 16 + threadIdx.x - 16] = 0.f;
    }
    int t = blockIdx.x * blockDim.x + threadIdx.x;
    if (t >= CI * H * 48) return;
    int k2 = t % 48;
    int Y  = (t / 48) % H;
    int ch = t / (48 * H);

    int m = Y >> 2, i = Y & 3;
    int y0, y1;
    float wy;
    if (i < 2) { y0 = max(m - 1, 0); y1 = m; wy = (i == 0) ? 0.625f : 0.875f; }
    else       { y0 = m; y1 = min(m + 1, h_ - 1); wy = (i == 2) ? 0.125f : 0.375f; }

    const float* pl = g_msgo + (size_t)(b * CI + ch) * N;
    int x0 = 2 * k2;
    int xm = max(x0 - 1, 0), x1 = x0 + 1, x2 = min(x0 + 2, w_ - 1);
    const float* r0p = pl + y0 * w_;
    const float* r1p = pl + y1 * w_;
    float wy1 = 1.f - wy;
    float pm = wy1 * r0p[xm] + wy * r1p[xm];
    float p0 = wy1 * r0p[x0] + wy * r1p[x0];
    float p1 = wy1 * r0p[x1] + wy * r1p[x1];
    float p2 = wy1 * r0p[x2] + wy * r1p[x2];

    float A = alpha[0];
    size_t base = ((size_t)b * CI * H * 48 + t) * 8;
    float4 i0 = __ldcs((const float4*)(img + base));
    float4 i1 = __ldcs((const float4*)(img + base + 4));
    float4 o0, o1;
    o0.x = i0.x + A * (0.375f * pm + 0.625f * p0);
    o0.y = i0.y + A * (0.125f * pm + 0.875f * p0);
    o0.z = i0.z + A * (0.875f * p0 + 0.125f * p1);
    o0.w = i0.w + A * (0.625f * p0 + 0.375f * p1);
    o1.x = i1.x + A * (0.375f * p0 + 0.625f * p1);
    o1.y = i1.y + A * (0.125f * p0 + 0.875f * p1);
    o1.z = i1.z + A * (0.875f * p1 + 0.125f * p2);
    o1.w = i1.w + A * (0.625f * p1 + 0.375f * p2);
    __stcs((float4*)(out + base),     o0);
    __stcs((float4*)(out + base + 4), o1);
}

// ---------------- launch: R12 fork-join (proven best DAG) -----------------
extern "C" void kernel_launch(void* const* d_in, const int* in_sizes, int n_in,
                              void* d_out, int out_size) {
    const float* img_bev  = (const float*)d_in[0];
    const float* rad_bev  = (const float*)d_in[1];
    const float* occ_prob = (const float*)d_in[2];
    const float* Wq    = (const float*)d_in[3];
    const float* Wk    = (const float*)d_in[4];
    const float* Wv    = (const float*)d_in[5];
    const float* Wo    = (const float*)d_in[6];
    const float* gq_w  = (const float*)d_in[7];
    const float* gq_b  = (const float*)d_in[8];
    const float* gk_w  = (const float*)d_in[9];
    const float* gk_b  = (const float*)d_in[10];
    const float* alpha = (const float*)d_in[11];
    float* out = (float*)d_out;

    // Lazily create streams/events on the FIRST (uncaptured) call.
    static cudaStream_t s[2];
    static cudaEvent_t ev_root, ev_done[2];
    static bool init = false;
    if (!init) {
        cudaStreamCreateWithFlags(&s[0], cudaStreamNonBlocking);
        cudaStreamCreateWithFlags(&s[1], cudaStreamNonBlocking);
        cudaEventCreateWithFlags(&ev_root,    cudaEventDisableTiming);
        cudaEventCreateWithFlags(&ev_done[0], cudaEventDisableTiming);
        cudaEventCreateWithFlags(&ev_done[1], cudaEventDisableTiming);
        init = true;
    }

    // fork from the captured stream
    cudaEventRecord(ev_root, 0);
    cudaStreamWaitEvent(s[0], ev_root, 0);
    cudaStreamWaitEvent(s[1], ev_root, 0);

    dim3 ag(w_ / TX, h_ / TY, 1);
    dim3 wg(N / 128, CI / 64, 1);
    for (int b = 0; b < 2; b++) {
        front_kernel<<<324, 256, 0, s[b]>>>(b, img_bev, rad_bev, occ_prob, Wq, Wk, Wv);
        attn_kernel<<<ag, 256, 0, s[b]>>>(b, gq_w, gq_b, gk_w, gk_b);
        wo_kernel<<<wg, 256, 0, s[b]>>>(b, Wo);
        upsample_add<<<CI * H * 48 / 256, 256, 0, s[b]>>>(b, img_bev, alpha, out);
    }

    // join back to the captured stream
    cudaEventRecord(ev_done[0], s[0]);
    cudaEventRecord(ev_done[1], s[1]);
    cudaStreamWaitEvent(0, ev_done[0], 0);
    cudaStreamWaitEvent(0, ev_done[1], 0);
}

// round 16
// speedup vs baseline: 1.2170x; 1.0090x over previous
#include <cuda_runtime.h>

// ---------------- problem constants ----------------
constexpr int B   = 2;
constexpr int CI  = 256;
constexpr int CR  = 128;
constexpr int H   = 384;
constexpr int W   = 384;
constexpr int h_  = 96;
constexpr int w_  = 96;
constexpr int N   = h_ * w_;       // 9216
constexpr int D   = 64;
constexpr int GRP = 8;

// attention tile geometry: 8x4 pixels, 8 threads/pixel (channel octets)
constexpr int TX = 8;
constexpr int TY = 4;
constexpr int HC = TX + 6;         // 14
constexpr int HR = TY + 6;         // 10
constexpr int NCOL = HC * HR;      // 140
constexpr int C4STR = 18;          // float4 stride per col => ≡2 mod 8, conflict-free

// ---------------- scratch ----------------
__device__ float g_locc[B * N];
__device__ float g_gate[B * N];
__device__ float g_q[B * N * D];
__device__ float g_k[B * N * D];
__device__ float g_v[B * N * D];
__device__ float g_msg[B * N * D];
__device__ float g_msgo[B * CI * N];
__device__ float g_qstats[B * GRP * 2];   // [b*16 .. b*16+16)
__device__ float g_kstats[B * GRP * 2];

// ---------------- f32x2 packed-FMA helpers ----------------
__device__ __forceinline__ unsigned long long ffma2(unsigned long long a,
                                                    unsigned long long b,
                                                    unsigned long long c) {
    unsigned long long d;
    asm("fma.rn.f32x2 %0, %1, %2, %3;" : "=l"(d) : "l"(a), "l"(b), "l"(c));
    return d;
}
__device__ __forceinline__ unsigned long long pack2(float x) {
    unsigned long long d;
    asm("mov.b64 %0, {%1, %2};" : "=l"(d)
        : "r"(__float_as_uint(x)), "r"(__float_as_uint(x)));
    return d;
}
__device__ __forceinline__ float2 ffma2v(float2 a, float2 b, float2 c) {
    float2 d;
    asm("fma.rn.f32x2 %0, %1, %2, %3;"
        : "=l"(reinterpret_cast<unsigned long long&>(d))
        : "l"(reinterpret_cast<unsigned long long&>(a)),
          "l"(reinterpret_cast<unsigned long long&>(b)),
          "l"(reinterpret_cast<unsigned long long&>(c)));
    return d;
}

// ================= per-batch front kernel =================
// blocks [0,144): fused avgpool+Wq proj (+GN q stats), 64n x 64o tile
// blocks [144,288): fused maxpool+Wk/Wv proj (+GN k stats)
// blocks [288,324): occ maxpool -> locc/gate
__global__ __launch_bounds__(256) void front_kernel(
    int b,
    const float* __restrict__ img, const float* __restrict__ rad,
    const float* __restrict__ occ,
    const float* __restrict__ Wq, const float* __restrict__ Wk,
    const float* __restrict__ Wv) {
    __shared__ __align__(16) float sm[2 * 2176 + 2048];   // 25.6 KB
    int bid = blockIdx.x;
    int tid = threadIdx.x;

    if (bid < 144) {
        // ---------------- proj_q: 64n x 64o, K-tile 32 ----------------
        float* Ws = sm;            // [c][o] stride 68
        float* Is = sm + 2176;     // [c][n] 32x64
        int n0 = bid * 64;
        int tx = tid & 15;
        int ty = tid >> 4;
        float acc[4][4] = {};

        for (int c0 = 0; c0 < CI; c0 += 32) {
            for (int i = tid; i < 2048; i += 256) {
                int c = i & 31, o = i >> 5;
                Ws[c * 68 + o] = Wq[o * CI + c0 + c];
            }
            for (int i = tid; i < 2048; i += 256) {
                int c = i >> 6, x = i & 63;
                int n = n0 + x;
                int yy = n / 96, xx = n - yy * 96;
                const float* p = img + (((size_t)(b * CI + c0 + c) * H + yy * 4) * W) + xx * 4;
                float s = 0.f;
#pragma unroll
                for (int r = 0; r < 4; r++) {
                    float4 v = __ldcs((const float4*)(p + r * W));
                    s += v.x + v.y + v.z + v.w;
                }
                Is[c * 64 + x] = s * 0.0625f;
            }
            __syncthreads();
#pragma unroll
            for (int c = 0; c < 32; c++) {
                float4 a4 = *(const float4*)&Ws[c * 68 + ty * 4];
                float4 b4 = *(const float4*)&Is[c * 64 + tx * 4];
                acc[0][0] += a4.x * b4.x; acc[0][1] += a4.x * b4.y;
                acc[0][2] += a4.x * b4.z; acc[0][3] += a4.x * b4.w;
                acc[1][0] += a4.y * b4.x; acc[1][1] += a4.y * b4.y;
                acc[1][2] += a4.y * b4.z; acc[1][3] += a4.y * b4.w;
                acc[2][0] += a4.z * b4.x; acc[2][1] += a4.z * b4.y;
                acc[2][2] += a4.z * b4.z; acc[2][3] += a4.z * b4.w;
                acc[3][0] += a4.w * b4.x; acc[3][1] += a4.w * b4.y;
                acc[3][2] += a4.w * b4.z; acc[3][3] += a4.w * b4.w;
            }
            __syncthreads();
        }

        float s = 0.f, s2 = 0.f;
#pragma unroll
        for (int j = 0; j < 4; j++) {
            float4 o4 = make_float4(acc[0][j], acc[1][j], acc[2][j], acc[3][j]);
            *(float4*)(g_q + ((size_t)(b * N + n0 + tx * 4 + j)) * 64 + ty * 4) = o4;
            s  += o4.x + o4.y + o4.z + o4.w;
            s2 += o4.x * o4.x + o4.y * o4.y + o4.z * o4.z + o4.w * o4.w;
        }
#pragma unroll
        for (int off = 16; off; off >>= 1) {
            s  += __shfl_down_sync(0xffffffffu, s,  off);
            s2 += __shfl_down_sync(0xffffffffu, s2, off);
        }
        if ((tid & 31) == 0) {
            int g = tid >> 5;
            atomicAdd(&g_qstats[(b * 8 + g) * 2 + 0], s);
            atomicAdd(&g_qstats[(b * 8 + g) * 2 + 1], s2);
        }
    } else if (bid < 288) {
        // ---------------- proj_kv: 64n x 64o ----------------
        float* Wks = sm;
        float* Wvs = sm + 2176;
        float* Is  = sm + 4352;
        int n0 = (bid - 144) * 64;
        int tx = tid & 15;
        int ty = tid >> 4;
        float ak[4][4] = {};
        float av[4][4] = {};

        for (int c0 = 0; c0 < CR; c0 += 32) {
            for (int i = tid; i < 2048; i += 256) {
                int c = i & 31, o = i >> 5;
                Wks[c * 68 + o] = Wk[o * CR + c0 + c];
                Wvs[c * 68 + o] = Wv[o * CR + c0 + c];
            }
            for (int i = tid; i < 2048; i += 256) {
                int c = i >> 6, x = i & 63;
                int n = n0 + x;
                int yy = n / 96, xx = n - yy * 96;
                const float* p = rad + (((size_t)(b * CR + c0 + c) * H + yy * 4) * W) + xx * 4;
                float m = -3.4e38f;
#pragma unroll
                for (int r = 0; r < 4; r++) {
                    float4 v = __ldcs((const float4*)(p + r * W));
                    m = fmaxf(m, fmaxf(fmaxf(v.x, v.y), fmaxf(v.z, v.w)));
                }
                Is[c * 64 + x] = m;
            }
            __syncthreads();
#pragma unroll
            for (int c = 0; c < 32; c++) {
                float4 ka = *(const float4*)&Wks[c * 68 + ty * 4];
                float4 va = *(const float4*)&Wvs[c * 68 + ty * 4];
                float4 b4 = *(const float4*)&Is[c * 64 + tx * 4];
                ak[0][0] += ka.x * b4.x; ak[0][1] += ka.x * b4.y;
                ak[0][2] += ka.x * b4.z; ak[0][3] += ka.x * b4.w;
                ak[1][0] += ka.y * b4.x; ak[1][1] += ka.y * b4.y;
                ak[1][2] += ka.y * b4.z; ak[1][3] += ka.y * b4.w;
                ak[2][0] += ka.z * b4.x; ak[2][1] += ka.z * b4.y;
                ak[2][2] += ka.z * b4.z; ak[2][3] += ka.z * b4.w;
                ak[3][0] += ka.w * b4.x; ak[3][1] += ka.w * b4.y;
                ak[3][2] += ka.w * b4.z; ak[3][3] += ka.w * b4.w;
                av[0][0] += va.x * b4.x; av[0][1] += va.x * b4.y;
                av[0][2] += va.x * b4.z; av[0][3] += va.x * b4.w;
                av[1][0] += va.y * b4.x; av[1][1] += va.y * b4.y;
                av[1][2] += va.y * b4.z; av[1][3] += va.y * b4.w;
                av[2][0] += va.z * b4.x; av[2][1] += va.z * b4.y;
                av[2][2] += va.z * b4.z; av[2][3] += va.z * b4.w;
                av[3][0] += va.w * b4.x; av[3][1] += va.w * b4.y;
                av[3][2] += va.w * b4.z; av[3][3] += va.w * b4.w;
            }
            __syncthreads();
        }

        float s = 0.f, s2 = 0.f;
#pragma unroll
        for (int j = 0; j < 4; j++) {
            size_t row = ((size_t)(b * N + n0 + tx * 4 + j)) * 64 + ty * 4;
            float4 k4 = make_float4(ak[0][j], ak[1][j], ak[2][j], ak[3][j]);
            float4 v4 = make_float4(av[0][j], av[1][j], av[2][j], av[3][j]);
            *(float4*)(g_k + row) = k4;
            *(float4*)(g_v + row) = v4;
            s  += k4.x + k4.y + k4.z + k4.w;
            s2 += k4.x * k4.x + k4.y * k4.y + k4.z * k4.z + k4.w * k4.w;
        }
#pragma unroll
        for (int off = 16; off; off >>= 1) {
            s  += __shfl_down_sync(0xffffffffu, s,  off);
            s2 += __shfl_down_sync(0xffffffffu, s2, off);
        }
        if ((tid & 31) == 0) {
            int g = tid >> 5;
            atomicAdd(&g_kstats[(b * 8 + g) * 2 + 0], s);
            atomicAdd(&g_kstats[(b * 8 + g) * 2 + 1], s2);
        }
    } else {
        // ---------------- pool_occ (per batch) ----------------
        int t = (bid - 288) * 256 + tid;
        if (t >= N) return;
        int x = t % w_;
        int y = t / w_;
        const float* p = occ + ((size_t)b * H + y * 4) * W + x * 4;
        float m = -3.4e38f;
#pragma unroll
        for (int r = 0; r < 4; r++) {
            float4 v = __ldcs((const float4*)(p + r * W));
            m = fmaxf(m, fmaxf(fmaxf(v.x, v.y), fmaxf(v.z, v.w)));
        }
        g_locc[b * N + t] = 2.f * logf(fmaxf(m, 1e-6f));
        g_gate[b * N + t] = fminf(fmaxf(m, 0.f), 1.f);
    }
}

// ------------- attention: 8 threads/pixel (per batch) ----------------
__global__ __launch_bounds__(256, 4)
void attn_kernel(int b,
                 const float* __restrict__ gq_w, const float* __restrict__ gq_b,
                 const float* __restrict__ gk_w, const float* __restrict__ gk_b) {
    __shared__ float4 kv_s[NCOL * C4STR];
    __shared__ float  w_s[32 * 49];
    __shared__ float  locc_s[NCOL];
    __shared__ float  sQA[64], sQB[64], sAk[64], sBk[64];

    int x0 = blockIdx.x * TX, y0 = blockIdx.y * TY;
    int tid  = threadIdx.x;
    int wrp  = tid >> 5;
    int lane = tid & 31;
    int r    = wrp >> 1;
    int pix  = (wrp & 1) * 4 + (lane & 3);
    int oct  = lane >> 2;

    if (tid < 64) {
        int d = tid, g = d >> 3;
        const float inv = 1.f / (float)(N * 8);
        float su  = g_qstats[(b * 8 + g) * 2 + 0];
        float su2 = g_qstats[(b * 8 + g) * 2 + 1];
        float mu = su * inv;
        float rs = rsqrtf(su2 * inv - mu * mu + 1e-5f);
        float A = rs * gq_w[d];
        sQA[d] = A;
        sQB[d] = gq_b[d] - mu * A;
        su  = g_kstats[(b * 8 + g) * 2 + 0];
        su2 = g_kstats[(b * 8 + g) * 2 + 1];
        mu = su * inv;
        rs = rsqrtf(su2 * inv - mu * mu + 1e-5f);
        A = rs * gk_w[d];
        sAk[d] = A;
        sBk[d] = gk_b[d] - mu * A;
    }

    for (int i = tid; i < NCOL * 16; i += 256) {
        int col = i >> 4, quad = i & 15;
        int rr = col / HC, cc = col - rr * HC;
        int yy = y0 - 3 + rr, xx = x0 - 3 + cc;
        bool ok = ((unsigned)yy < (unsigned)h_) && ((unsigned)xx < (unsigned)w_);
        int nn = b * N + yy * w_ + xx;
        float4 v = make_float4(0.f, 0.f, 0.f, 0.f);
        if (ok) v = *(const float4*)(g_k + (size_t)nn * 64 + quad * 4);
        kv_s[col * C4STR + quad] = v;
        if (quad == 0) locc_s[col] = ok ? g_locc[nn] : 0.f;
    }
    __syncthreads();

    int nq = b * N + (y0 + r) * w_ + x0 + pix;

    float2 qp[4];
    float qB;
    {
        const float* qr = g_q + (size_t)nq * 64;
        float4 qa = *(const float4*)(qr + oct * 4);
        float4 qb = *(const float4*)(qr + 32 + oct * 4);
        int da = oct * 4, db = 32 + oct * 4;
        float n0 = qa.x * sQA[da + 0] + sQB[da + 0];
        float n1 = qa.y * sQA[da + 1] + sQB[da + 1];
        float n2 = qa.z * sQA[da + 2] + sQB[da + 2];
        float n3 = qa.w * sQA[da + 3] + sQB[da + 3];
        float n4 = qb.x * sQA[db + 0] + sQB[db + 0];
        float n5 = qb.y * sQA[db + 1] + sQB[db + 1];
        float n6 = qb.z * sQA[db + 2] + sQB[db + 2];
        float n7 = qb.w * sQA[db + 3] + sQB[db + 3];
        qB = n0 * sBk[da + 0] + n1 * sBk[da + 1] + n2 * sBk[da + 2] + n3 * sBk[da + 3]
           + n4 * sBk[db + 0] + n5 * sBk[db + 1] + n6 * sBk[db + 2] + n7 * sBk[db + 3];
        qp[0] = make_float2(n0 * sAk[da + 0] * 0.125f, n1 * sAk[da + 1] * 0.125f);
        qp[1] = make_float2(n2 * sAk[da + 2] * 0.125f, n3 * sAk[da + 3] * 0.125f);
        qp[2] = make_float2(n4 * sAk[db + 0] * 0.125f, n5 * sAk[db + 1] * 0.125f);
        qp[3] = make_float2(n6 * sAk[db + 2] * 0.125f, n7 * sAk[db + 3] * 0.125f);
    }
    qB += __shfl_xor_sync(0xffffffffu, qB, 4);
    qB += __shfl_xor_sync(0xffffffffu, qB, 8);
    qB += __shfl_xor_sync(0xffffffffu, qB, 16);
    float qB2 = qB * 0.125f;

    const float LPAD = -27.631021115928547f;
    const float4* kbase = &kv_s[(r * HC + pix) * C4STR];

    float lg[7];
    float m_own = -1e30f;

#pragma unroll
    for (int p = 0; p < 49; p++) {
        int dy = p / 7, dx = p - dy * 7;
        const float4* kp = kbase + (dy * HC + dx) * C4STR;
        float4 ka = kp[oct];
        float4 kb = kp[oct + 8];
        float2 a2 = make_float2(0.f, 0.f);
        a2 = ffma2v(qp[0], make_float2(ka.x, ka.y), a2);
        a2 = ffma2v(qp[2], make_float2(kb.x, kb.y), a2);
        float2 b2 = make_float2(0.f, 0.f);
        b2 = ffma2v(qp[1], make_float2(ka.z, ka.w), b2);
        b2 = ffma2v(qp[3], make_float2(kb.z, kb.w), b2);
        float dot = a2.x + a2.y + b2.x + b2.y;
        dot += __shfl_xor_sync(0xffffffffu, dot, 4);
        dot += __shfl_xor_sync(0xffffffffu, dot, 8);
        dot += __shfl_xor_sync(0xffffffffu, dot, 16);

        if (oct == (p & 7)) {
            int yy = y0 + r + dy - 3;
            int xx = x0 + pix + dx - 3;
            bool inb = ((unsigned)yy < (unsigned)h_) && ((unsigned)xx < (unsigned)w_);
            int col = (r + dy) * HC + pix + dx;
            float logit = inb ? (dot + qB2 + locc_s[col]) : LPAD;
            lg[p >> 3] = logit;
            m_own = fmaxf(m_own, logit);
        }
    }

    m_own = fmaxf(m_own, __shfl_xor_sync(0xffffffffu, m_own, 4));
    m_own = fmaxf(m_own, __shfl_xor_sync(0xffffffffu, m_own, 8));
    m_own = fmaxf(m_own, __shfl_xor_sync(0xffffffffu, m_own, 16));
    int px_idx = r * 8 + pix;
    float* wr = &w_s[px_idx * 49];
    float ssum = 0.f;
#pragma unroll
    for (int g = 0; g < 7; g++) {
        if (g < 6 || oct == 0) {
            float e = __expf(lg[g] - m_own);
            ssum += e;
            wr[g * 8 + oct] = e;
        }
    }
    ssum += __shfl_xor_sync(0xffffffffu, ssum, 4);
    ssum += __shfl_xor_sync(0xffffffffu, ssum, 8);
    ssum += __shfl_xor_sync(0xffffffffu, ssum, 16);
    float gs = g_gate[nq] / ssum;

    __syncthreads();
    for (int i = tid; i < NCOL * 16; i += 256) {
        int col = i >> 4, quad = i & 15;
        int rr = col / HC, cc = col - rr * HC;
        int yy = y0 - 3 + rr, xx = x0 - 3 + cc;
        bool ok = ((unsigned)yy < (unsigned)h_) && ((unsigned)xx < (unsigned)w_);
        float4 v = make_float4(0.f, 0.f, 0.f, 0.f);
        if (ok) v = *(const float4*)(g_v + ((size_t)(b * N + yy * w_ + xx)) * 64 + quad * 4);
        kv_s[col * C4STR + quad] = v;
    }
    __syncthreads();

    float2 acc[4];
#pragma unroll
    for (int c = 0; c < 4; c++) acc[c] = make_float2(0.f, 0.f);
#pragma unroll
    for (int p = 0; p < 49; p++) {
        int dy = p / 7, dx = p - dy * 7;
        float wgt = wr[p];
        float2 w2 = make_float2(wgt, wgt);
        const float4* vp = kbase + (dy * HC + dx) * C4STR;
        float4 va = vp[oct];
        float4 vb = vp[oct + 8];
        acc[0] = ffma2v(w2, make_float2(va.x, va.y), acc[0]);
        acc[1] = ffma2v(w2, make_float2(va.z, va.w), acc[1]);
        acc[2] = ffma2v(w2, make_float2(vb.x, vb.y), acc[2]);
        acc[3] = ffma2v(w2, make_float2(vb.z, vb.w), acc[3]);
    }
    float* mp = g_msg + (size_t)nq * 64;
    *(float4*)(mp + oct * 4)      = make_float4(acc[0].x * gs, acc[0].y * gs,
                                                acc[1].x * gs, acc[1].y * gs);
    *(float4*)(mp + 32 + oct * 4) = make_float4(acc[2].x * gs, acc[2].y * gs,
                                                acc[3].x * gs, acc[3].y * gs);
}

// ---------------- Wo projection with packed f32x2 FMA (per batch) ---------
__global__ __launch_bounds__(256) void wo_kernel(int b, const float* __restrict__ Wo) {
    __shared__ float Ws[32 * 132];
    __shared__ float Ms[32 * 132];
    int co0 = blockIdx.y * 128;
    int n0  = blockIdx.x * 128;
    int tid = threadIdx.x;
    int tx = tid & 15;
    int ty = tid >> 4;

    unsigned long long acc[8][4] = {};

    for (int kc = 0; kc < 2; kc++) {
        int d0 = kc * 32;
        for (int idx = tid; idx < 1024; idx += 256) {
            int r = idx >> 3, dq = idx & 7;
            float4 v = *(const float4*)(Wo + (size_t)(co0 + r) * 64 + d0 + dq * 4);
            Ws[(dq * 4 + 0) * 132 + r] = v.x;
            Ws[(dq * 4 + 1) * 132 + r] = v.y;
            Ws[(dq * 4 + 2) * 132 + r] = v.z;
            Ws[(dq * 4 + 3) * 132 + r] = v.w;
            float4 u = *(const float4*)(g_msg + ((size_t)(b * N + n0 + r)) * 64 + d0 + dq * 4);
            Ms[(dq * 4 + 0) * 132 + r] = u.x;
            Ms[(dq * 4 + 1) * 132 + r] = u.y;
            Ms[(dq * 4 + 2) * 132 + r] = u.z;
            Ms[(dq * 4 + 3) * 132 + r] = u.w;
        }
        __syncthreads();
#pragma unroll
        for (int d = 0; d < 32; d++) {
            unsigned long long b2[4];
#pragma unroll
            for (int jp = 0; jp < 4; jp++)
                b2[jp] = *(const unsigned long long*)&Ms[d * 132 + tx * 8 + jp * 2];
#pragma unroll
            for (int i = 0; i < 8; i++) {
                unsigned long long a2 = pack2(Ws[d * 132 + ty * 8 + i]);
#pragma unroll
                for (int jp = 0; jp < 4; jp++)
                    acc[i][jp] = ffma2(a2, b2[jp], acc[i][jp]);
            }
        }
        __syncthreads();
    }
#pragma unroll
    for (int i = 0; i < 8; i++) {
        float2 r0 = *(float2*)&acc[i][0];
        float2 r1 = *(float2*)&acc[i][1];
        float2 r2 = *(float2*)&acc[i][2];
        float2 r3 = *(float2*)&acc[i][3];
        float* dst = g_msgo + ((size_t)(b * CI + co0 + ty * 8 + i)) * N + n0 + tx * 8;
        *(float4*)dst       = make_float4(r0.x, r0.y, r1.x, r1.y);
        *(float4*)(dst + 4) = make_float4(r2.x, r2.y, r3.x, r3.y);
    }
}

// ------- bilinear x4 upsample + residual (per batch); zero own stats ------
__global__ void upsample_add(int b, const float* __restrict__ img,
                             const float* __restrict__ alpha,
                             float* __restrict__ out) {
    if (blockIdx.x == 0 && threadIdx.x < 32) {
        if (threadIdx.x < 16) g_qstats[b * 16 + threadIdx.x] = 0.f;
        else                  g_kstats[b * 16 + threadIdx.x - 16] = 0.f;
    }
    int t = blockIdx.x * blockDim.x + threadIdx.x;
    if (t >= CI * H * 48) return;
    int k2 = t % 48;
    int Y  = (t / 48) % H;
    int ch = t / (48 * H);

    int m = Y >> 2, i = Y & 3;
    int y0, y1;
    float wy;
    if (i < 2) { y0 = max(m - 1, 0); y1 = m; wy = (i == 0) ? 0.625f : 0.875f; }
    else       { y0 = m; y1 = min(m + 1, h_ - 1); wy = (i == 2) ? 0.125f : 0.375f; }

    const float* pl = g_msgo + (size_t)(b * CI + ch) * N;
    int x0 = 2 * k2;
    int xm = max(x0 - 1, 0), x1 = x0 + 1, x2 = min(x0 + 2, w_ - 1);
    const float* r0p = pl + y0 * w_;
    const float* r1p = pl + y1 * w_;
    float wy1 = 1.f - wy;
    float pm = wy1 * r0p[xm] + wy * r1p[xm];
    float p0 = wy1 * r0p[x0] + wy * r1p[x0];
    float p1 = wy1 * r0p[x1] + wy * r1p[x1];
    float p2 = wy1 * r0p[x2] + wy * r1p[x2];

    float A = alpha[0];
    size_t base = ((size_t)b * CI * H * 48 + t) * 8;
    float4 i0 = __ldcs((const float4*)(img + base));
    float4 i1 = __ldcs((const float4*)(img + base + 4));
    float4 o0, o1;
    o0.x = i0.x + A * (0.375f * pm + 0.625f * p0);
    o0.y = i0.y + A * (0.125f * pm + 0.875f * p0);
    o0.z = i0.z + A * (0.875f * p0 + 0.125f * p1);
    o0.w = i0.w + A * (0.625f * p0 + 0.375f * p1);
    o1.x = i1.x + A * (0.375f * p0 + 0.625f * p1);
    o1.y = i1.y + A * (0.125f * p0 + 0.875f * p1);
    o1.z = i1.z + A * (0.875f * p1 + 0.125f * p2);
    o1.w = i1.w + A * (0.625f * p1 + 0.375f * p2);
    __stcs((float4*)(out + base),     o0);
    __stcs((float4*)(out + base + 4), o1);
}

// ---------------- launch: fork the two batch pipelines --------------------
extern "C" void kernel_launch(void* const* d_in, const int* in_sizes, int n_in,
                              void* d_out, int out_size) {
    const float* img_bev  = (const float*)d_in[0];
    const float* rad_bev  = (const float*)d_in[1];
    const float* occ_prob = (const float*)d_in[2];
    const float* Wq    = (const float*)d_in[3];
    const float* Wk    = (const float*)d_in[4];
    const float* Wv    = (const float*)d_in[5];
    const float* Wo    = (const float*)d_in[6];
    const float* gq_w  = (const float*)d_in[7];
    const float* gq_b  = (const float*)d_in[8];
    const float* gk_w  = (const float*)d_in[9];
    const float* gk_b  = (const float*)d_in[10];
    const float* alpha = (const float*)d_in[11];
    float* out = (float*)d_out;

    // Lazily create streams/events on the FIRST call (the uncaptured
    // correctness run), so no resource creation happens during capture.
    static cudaStream_t s[2];
    static cudaEvent_t ev_root, ev_done[2];
    static bool init = false;
    if (!init) {
        cudaStreamCreateWithFlags(&s[0], cudaStreamNonBlocking);
        cudaStreamCreateWithFlags(&s[1], cudaStreamNonBlocking);
        cudaEventCreateWithFlags(&ev_root,    cudaEventDisableTiming);
        cudaEventCreateWithFlags(&ev_done[0], cudaEventDisableTiming);
        cudaEventCreateWithFlags(&ev_done[1], cudaEventDisableTiming);
        init = true;
    }

    // fork from the launch (captured) stream
    cudaEventRecord(ev_root, 0);
    cudaStreamWaitEvent(s[0], ev_root, 0);
    cudaStreamWaitEvent(s[1], ev_root, 0);

    dim3 ag(w_ / TX, h_ / TY, 1);
    dim3 wg(N / 128, CI / 128, 1);
    for (int b = 0; b < 2; b++) {
        front_kernel<<<324, 256, 0, s[b]>>>(b, img_bev, rad_bev, occ_prob, Wq, Wk, Wv);
        attn_kernel<<<ag, 256, 0, s[b]>>>(b, gq_w, gq_b, gk_w, gk_b);
        wo_kernel<<<wg, 256, 0, s[b]>>>(b, Wo);
        upsample_add<<<CI * H * 48 / 256, 256, 0, s[b]>>>(b, img_bev, alpha, out);
    }

    // join back to the captured stream
    cudaEventRecord(ev_done[0], s[0]);
    cudaEventRecord(ev_done[1], s[1]);
    cudaStreamWaitEvent(0, ev_done[0], 0);
    cudaStreamWaitEvent(0, ev_done[1], 0);
}